// round 11
// baseline (speedup 1.0000x reference)
#include <cuda_runtime.h>

// Grouped 1x7 conv (NCHW, groups=2, shared weights) + roll(H), tensor cores
// (m16n8k8 tf32, 3xTF32 precision recovery).
//
// Kernel 1: one-time split of w into (tf32_hi, tf32_lo) uint2 scratch,
//           GEMM layout [oc][kw*24+ic], padded stride SWS=172.
// Kernel 2: block = (h-PAIR, g, m-half): 48 oc x 2 rows (112 pixels).
//           grid (28,2,2) = 112 blocks -> one balanced CTA per SM.
//           12 warps = (mt 0..2) x (nq 0..3), frags per nq = {4,4,3,3} of 14.
//           Weight tile (66KB) via one cp.async.bulk; reused for BOTH rows.

#define Hdim 56
#define Wdim 56
#define HW   3136
#define ICg  24
#define KW   7
#define SWS  172   // u64 stride per A row (168 used)
#define SXS  68    // u64 stride per x ic (62 used)

#define W_TILE_BYTES (48 * SWS * 8)                  // 66048
#define SX_BYTES     (2 * ICg * SXS * 8)             // 26112
#define MBAR_OFF     (W_TILE_BYTES + SX_BYTES)       // 92160

__device__ __align__(16) uint2 g_wsplit[96 * SWS];   // 132 KB scratch

__device__ __forceinline__ unsigned tf32_rna(float x) {
    unsigned r;
    asm("cvt.rna.tf32.f32 %0, %1;" : "=r"(r) : "f"(x));
    return r;
}

__device__ __forceinline__ void mma_tf32(float c[4],
                                         unsigned a0, unsigned a1,
                                         unsigned a2, unsigned a3,
                                         unsigned b0, unsigned b1) {
    asm volatile(
        "mma.sync.aligned.m16n8k8.row.col.f32.tf32.tf32.f32 "
        "{%0,%1,%2,%3},{%4,%5,%6,%7},{%8,%9},{%0,%1,%2,%3};"
        : "+f"(c[0]), "+f"(c[1]), "+f"(c[2]), "+f"(c[3])
        : "r"(a0), "r"(a1), "r"(a2), "r"(a3), "r"(b0), "r"(b1));
}

__global__ __launch_bounds__(256, 4)
void split_w_kernel(const float* __restrict__ w)
{
    int i = blockIdx.x * 256 + threadIdx.x;
    if (i >= ICg * 96 * KW) return;          // 16128
    int ic = i / 672;
    int r  = i - ic * 672;
    int oc = r / 7;
    int kw = r - oc * 7;
    float v = w[i];
    unsigned hi = tf32_rna(v);
    float lo = v - __uint_as_float(hi);
    g_wsplit[oc * SWS + kw * ICg + ic] = make_uint2(hi, tf32_rna(lo));
}

__global__ __launch_bounds__(384, 1)
void conv1x7_tc5(const float* __restrict__ x,
                 const int* __restrict__ shift, float* __restrict__ out)
{
    extern __shared__ char smem[];
    uint2* sw = (uint2*)smem;                              // [48][SWS]
    uint2* sx = (uint2*)(smem + W_TILE_BYTES);             // [2*24][SXS]

    unsigned smem_base;
    asm("{ .reg .u64 t; cvta.to.shared.u64 t, %1; cvt.u32.u64 %0, t; }"
        : "=r"(smem_base) : "l"(smem));
    const unsigned mbar = smem_base + MBAR_OFF;

    const int tid = threadIdx.x;
    const int h0  = blockIdx.x * 2;
    const int g   = blockIdx.y;
    const int mh  = blockIdx.z;      // m-half: oc in [mh*48, mh*48+48)

    // ---- weights: single TMA bulk copy of this m-half's pre-split tile ----
    if (tid == 0) {
        asm volatile("mbarrier.init.shared.b64 [%0], 1;" :: "r"(mbar) : "memory");
        asm volatile("fence.proxy.async.shared::cta;" ::: "memory");
        asm volatile("mbarrier.arrive.expect_tx.shared.b64 _, [%0], %1;"
                     :: "r"(mbar), "r"((unsigned)W_TILE_BYTES) : "memory");
        asm volatile(
            "cp.async.bulk.shared::cta.global.mbarrier::complete_tx::bytes "
            "[%0], [%1], %2, [%3];"
            :: "r"(smem_base), "l"(g_wsplit + mh * 48 * SWS),
               "r"((unsigned)W_TILE_BYTES), "r"(mbar) : "memory");
    }

    // ---- stage + split 2 padded x rows: sx[(r*24+ic)][p] = split(x[ic][h0+r][p-3]) ----
    const float* xrow = x + (size_t)g * (ICg * HW) + h0 * Wdim;
    for (int i = tid; i < 2 * ICg * 64; i += 384) {        // 3072, 8 iters
        int p  = i & 63;
        int t  = i >> 6;          // 0..47
        int r  = t & 1;
        int ic = t >> 1;
        int wc = p - 3;
        float v = (wc >= 0 && wc < Wdim) ? xrow[ic * HW + r * Wdim + wc] : 0.f;
        unsigned hi = tf32_rna(v);
        float lo = v - __uint_as_float(hi);
        sx[(r * ICg + ic) * SXS + p] = make_uint2(hi, tf32_rna(lo));
    }
    __syncthreads();   // x stores + mbarrier init visible to all

    // wait for the bulk copy (phase 0)
    {
        unsigned done;
        asm volatile(
            "{\n\t.reg .pred p;\n\t"
            "mbarrier.try_wait.parity.acquire.cta.shared::cta.b64 p, [%1], 0;\n\t"
            "selp.b32 %0, 1, 0, p;\n\t}"
            : "=r"(done) : "r"(mbar) : "memory");
        while (!done) {
            asm volatile(
                "{\n\t.reg .pred p;\n\t"
                "mbarrier.try_wait.parity.acquire.cta.shared::cta.b64 p, [%1], 0, 0x989680;\n\t"
                "selp.b32 %0, 1, 0, p;\n\t}"
                : "=r"(done) : "r"(mbar) : "memory");
        }
    }

    const int wid  = tid >> 5;        // 0..11
    const int mt   = wid >> 2;        // local m-tile 0..2
    const int nq   = wid & 3;         // n-quarter 0..3
    const int nf   = (nq < 2) ? 4 : 3;
    const int nt0  = (nq < 2) ? nq * 4 : 8 + (nq - 2) * 3;   // 0,4,8,11
    const int lane = tid & 31;
    const int lg   = lane >> 2;       // 0..7
    const int lk   = lane & 3;        // 0..3

    const uint2* Abase = sw + (mt * 16 + lg) * SWS + lk;

    // per-fragment B base pointers (row + column resolved once)
    const uint2* px[4];
    #pragma unroll
    for (int f = 0; f < 4; f++) {
        int nt  = nt0 + f;
        int rr  = (nt >= 7) ? 1 : 0;
        int col = nt - rr * 7;
        px[f] = sx + (rr * ICg + lk) * SXS + col * 8 + lg;
    }

    float c[4][4];
    #pragma unroll
    for (int f = 0; f < 4; f++)
        #pragma unroll
        for (int q = 0; q < 4; q++) c[f][q] = 0.f;

    #pragma unroll
    for (int kw = 0; kw < KW; kw++) {
        #pragma unroll
        for (int ks = 0; ks < 3; ks++) {
            const int kb = kw * ICg + ks * 8;
            uint2 A0 = Abase[kb];
            uint2 A1 = Abase[kb + 8 * SWS];
            uint2 A2 = Abase[kb + 4];
            uint2 A3 = Abase[kb + 4 + 8 * SWS];

            uint2 B0[4], B1[4];
            #pragma unroll
            for (int f = 0; f < 4; f++) {
                if (f < nf) {
                    B0[f] = px[f][(ks * 8) * SXS + kw];
                    B1[f] = px[f][(ks * 8 + 4) * SXS + kw];
                }
            }

            // 3xTF32 passes; accumulator reuse distance = nf (3-4)
            #pragma unroll
            for (int f = 0; f < 4; f++)
                if (f < nf)
                    mma_tf32(c[f], A0.x, A1.x, A2.x, A3.x, B0[f].x, B1[f].x);
            #pragma unroll
            for (int f = 0; f < 4; f++)
                if (f < nf)
                    mma_tf32(c[f], A0.x, A1.x, A2.x, A3.x, B0[f].y, B1[f].y);
            #pragma unroll
            for (int f = 0; f < 4; f++)
                if (f < nf)
                    mma_tf32(c[f], A0.y, A1.y, A2.y, A3.y, B0[f].x, B1[f].x);
        }
    }

    // ---- roll + store ----
    const int s = *shift;
    int ho0 = (h0 + s) % Hdim;     if (ho0 < 0) ho0 += Hdim;
    int ho1 = (h0 + 1 + s) % Hdim; if (ho1 < 0) ho1 += Hdim;

    float* obase = out + (size_t)(g * 96 + mh * 48 + mt * 16 + lg) * HW + 2 * lk;
    #pragma unroll
    for (int f = 0; f < 4; f++) {
        if (f < nf) {
            int nt  = nt0 + f;
            int rr  = (nt >= 7) ? 1 : 0;
            int col = (nt - rr * 7) * 8;
            int ho  = rr ? ho1 : ho0;
            float* ob = obase + ho * Wdim + col;
            *(float2*)(ob)          = make_float2(c[f][0], c[f][1]);
            *(float2*)(ob + 8 * HW) = make_float2(c[f][2], c[f][3]);
        }
    }
}

extern "C" void kernel_launch(void* const* d_in, const int* in_sizes, int n_in,
                              void* d_out, int out_size)
{
    const float* x     = (const float*)d_in[0];
    const float* w     = (const float*)d_in[1];
    const int*   shift = (const int*)  d_in[2];
    float*       out   = (float*)d_out;

    split_w_kernel<<<63, 256>>>(w);    // 63*256 = 16128

    const int smem_bytes = MBAR_OFF + 16;   // 92176
    cudaFuncSetAttribute(conv1x7_tc5,
                         cudaFuncAttributeMaxDynamicSharedMemorySize, smem_bytes);

    dim3 grid(Hdim / 2, 2, 2);   // 28 h-pairs x 2 groups x 2 m-halves = 112 blocks
    conv1x7_tc5<<<grid, 384, smem_bytes>>>(x, shift, out);
}

// round 12
// speedup vs baseline: 1.1890x; 1.1890x over previous
#include <cuda_runtime.h>
#include <cuda_bf16.h>

// Grouped 1x7 conv (NCHW, groups=2, shared weights) + roll(H), tensor cores
// (m16n8k16 BF16, 3xBF16 split: hh + hl + lh, fp32 accumulate).
//
// K reordered as k = ic*8 + kw' (kw' 0..7, kw'=7 zero weight) so bf16x2 pairs
// are adjacent kw -> B pairs = adjacent pixels (sliding window), K' = 192 =
// 12 k16-chunks per pass.
//
// Kernel 1: split w into (bf16_hi, bf16_lo) uint2 pairs, layout
//           [oc][j] j = ic*4 + kw'/2, padded row stride SWP=100 u64.
// Kernel 2: block = (h, g, m-half): 48 oc x 56 pixels, 384 thr, 2 CTA/SM.
//           12 warps = (mt 0..2) x (nq 0..3), frags {2,2,2,1}.
//           Weight tile (37.5KB) via one cp.async.bulk.

#define Hdim 56
#define Wdim 56
#define HW   3136
#define ICg  24

#define SWP  100   // u64 stride per oc row (96 used)
#define SXP  64    // u64 stride per ic row of x pairs

#define W_TILE_BYTES (48 * SWP * 8)              // 38400
#define SX_BYTES     (ICg * SXP * 8)             // 12288
#define MBAR_OFF     (W_TILE_BYTES + SX_BYTES)   // 50688

__device__ __align__(16) uint2 g_wsplit[96 * SWP];   // 76.8 KB scratch

__device__ __forceinline__ unsigned bf16bits(float v) {
    return (unsigned)__bfloat16_as_ushort(__float2bfloat16_rn(v));
}

// pack (lo-k element v0, hi-k element v1) hi/lo split into one uint2
__device__ __forceinline__ uint2 split_pack(float v0, float v1) {
    unsigned h0 = bf16bits(v0);
    unsigned h1 = bf16bits(v1);
    float r0 = v0 - __bfloat162float(__ushort_as_bfloat16((unsigned short)h0));
    float r1 = v1 - __bfloat162float(__ushort_as_bfloat16((unsigned short)h1));
    unsigned l0 = bf16bits(r0);
    unsigned l1 = bf16bits(r1);
    return make_uint2(h0 | (h1 << 16), l0 | (l1 << 16));
}

__device__ __forceinline__ void mma_bf16(float c[4],
                                         unsigned a0, unsigned a1,
                                         unsigned a2, unsigned a3,
                                         unsigned b0, unsigned b1) {
    asm volatile(
        "mma.sync.aligned.m16n8k16.row.col.f32.bf16.bf16.f32 "
        "{%0,%1,%2,%3},{%4,%5,%6,%7},{%8,%9},{%0,%1,%2,%3};"
        : "+f"(c[0]), "+f"(c[1]), "+f"(c[2]), "+f"(c[3])
        : "r"(a0), "r"(a1), "r"(a2), "r"(a3), "r"(b0), "r"(b1));
}

__global__ __launch_bounds__(256, 4)
void split_w_bf(const float* __restrict__ w)
{
    int i = blockIdx.x * 256 + threadIdx.x;
    if (i >= 96 * 96) return;
    int oc = i / 96;
    int j  = i - oc * 96;          // j = ic*4 + t, pair kw' = 2t, 2t+1
    int ic = j >> 2;
    int t  = j & 3;
    const float* wp = w + ic * 672 + oc * 7;
    float v0 = wp[2 * t];
    float v1 = (2 * t + 1 < 7) ? wp[2 * t + 1] : 0.f;
    g_wsplit[oc * SWP + j] = split_pack(v0, v1);
}

__global__ __launch_bounds__(384, 2)
void conv1x7_bf(const float* __restrict__ x,
                const int* __restrict__ shift, float* __restrict__ out)
{
    extern __shared__ char smem[];
    uint2* swq = (uint2*)smem;                       // [48][SWP]
    uint2* sxp = (uint2*)(smem + W_TILE_BYTES);      // [24][SXP]

    unsigned smem_base;
    asm("{ .reg .u64 t; cvta.to.shared.u64 t, %1; cvt.u32.u64 %0, t; }"
        : "=r"(smem_base) : "l"(smem));
    const unsigned mbar = smem_base + MBAR_OFF;

    const int tid = threadIdx.x;
    const int h   = blockIdx.x;
    const int g   = blockIdx.y;
    const int mh  = blockIdx.z;      // oc in [mh*48, mh*48+48)

    // ---- weights: one TMA bulk copy of this m-half's pre-split tile ----
    if (tid == 0) {
        asm volatile("mbarrier.init.shared.b64 [%0], 1;" :: "r"(mbar) : "memory");
        asm volatile("fence.proxy.async.shared::cta;" ::: "memory");
        asm volatile("mbarrier.arrive.expect_tx.shared.b64 _, [%0], %1;"
                     :: "r"(mbar), "r"((unsigned)W_TILE_BYTES) : "memory");
        asm volatile(
            "cp.async.bulk.shared::cta.global.mbarrier::complete_tx::bytes "
            "[%0], [%1], %2, [%3];"
            :: "r"(smem_base), "l"(g_wsplit + mh * 48 * SWP),
               "r"((unsigned)W_TILE_BYTES), "r"(mbar) : "memory");
    }

    // ---- stage x row as split sliding-window pairs:
    //      sxp[ic][p] = split_pack(xq[p], xq[p+1]), xq[p] = x[ic][h][p-3] ----
    const float* xrow = x + (size_t)g * (ICg * HW) + h * Wdim;
    for (int i = tid; i < ICg * 64; i += 384) {      // 1536
        int ic = i >> 6;
        int p  = i & 63;
        int w0 = p - 3, w1 = p - 2;
        float v0 = (w0 >= 0 && w0 < Wdim) ? xrow[ic * HW + w0] : 0.f;
        float v1 = (w1 >= 0 && w1 < Wdim) ? xrow[ic * HW + w1] : 0.f;
        sxp[ic * SXP + p] = split_pack(v0, v1);
    }
    __syncthreads();   // x stores + mbarrier init visible

    // wait for the bulk copy (phase 0)
    {
        unsigned done;
        asm volatile(
            "{\n\t.reg .pred p;\n\t"
            "mbarrier.try_wait.parity.acquire.cta.shared::cta.b64 p, [%1], 0;\n\t"
            "selp.b32 %0, 1, 0, p;\n\t}"
            : "=r"(done) : "r"(mbar) : "memory");
        while (!done) {
            asm volatile(
                "{\n\t.reg .pred p;\n\t"
                "mbarrier.try_wait.parity.acquire.cta.shared::cta.b64 p, [%1], 0, 0x989680;\n\t"
                "selp.b32 %0, 1, 0, p;\n\t}"
                : "=r"(done) : "r"(mbar) : "memory");
        }
    }

    const int wid  = tid >> 5;        // 0..11
    const int mt   = wid >> 2;        // m-tile 0..2
    const int nq   = wid & 3;         // 0..3
    const int nf   = (nq == 3) ? 1 : 2;
    const int nt0  = nq * 2;          // frags nt0..nt0+nf-1 (7 total)
    const int lane = tid & 31;
    const int lg   = lane >> 2;       // 0..7
    const int lk   = lane & 3;        // 0..3

    const uint2* A0p = swq + (mt * 16 + lg) * SWP + lk;   // row lg
    const uint2* A1p = A0p + 8 * SWP;                     // row lg+8

    // B pixel index: p = n + 2*lk, n = (nt0+f)*8 + lg
    const int pb0 = nt0 * 8 + lg + 2 * lk;

    float c[2][4];
    #pragma unroll
    for (int f = 0; f < 2; f++)
        #pragma unroll
        for (int q = 0; q < 4; q++) c[f][q] = 0.f;

    #pragma unroll
    for (int ks = 0; ks < 12; ks++) {
        const int j = ks * 8;                 // +lk folded into pointer
        uint2 qa0 = A0p[j];                   // (hi, lo) of A row lg,   k 2lk..
        uint2 qa1 = A1p[j];                   // row lg+8
        uint2 qa2 = A0p[j + 4];               // k+8
        uint2 qa3 = A1p[j + 4];

        const uint2* b0p = sxp + (2 * ks) * SXP;       // ic = 2ks   (b0)
        const uint2* b1p = b0p + SXP;                  // ic = 2ks+1 (b1)

        uint2 B0[2], B1[2];
        #pragma unroll
        for (int f = 0; f < 2; f++) {
            if (f < nf) {
                B0[f] = b0p[pb0 + f * 8];
                B1[f] = b1p[pb0 + f * 8];
            }
        }

        // hh
        #pragma unroll
        for (int f = 0; f < 2; f++)
            if (f < nf)
                mma_bf16(c[f], qa0.x, qa1.x, qa2.x, qa3.x, B0[f].x, B1[f].x);
        // hl
        #pragma unroll
        for (int f = 0; f < 2; f++)
            if (f < nf)
                mma_bf16(c[f], qa0.x, qa1.x, qa2.x, qa3.x, B0[f].y, B1[f].y);
        // lh
        #pragma unroll
        for (int f = 0; f < 2; f++)
            if (f < nf)
                mma_bf16(c[f], qa0.y, qa1.y, qa2.y, qa3.y, B0[f].x, B1[f].x);
    }

    // ---- roll + store ----
    const int s = *shift;
    int ho = (h + s) % Hdim;
    if (ho < 0) ho += Hdim;

    float* ob = out + (size_t)(g * 96 + mh * 48 + mt * 16 + lg) * HW
                    + ho * Wdim + (nt0 * 8 + 2 * lk);
    #pragma unroll
    for (int f = 0; f < 2; f++) {
        if (f < nf) {
            *(float2*)(ob + f * 8)          = make_float2(c[f][0], c[f][1]);
            *(float2*)(ob + 8 * HW + f * 8) = make_float2(c[f][2], c[f][3]);
        }
    }
}

extern "C" void kernel_launch(void* const* d_in, const int* in_sizes, int n_in,
                              void* d_out, int out_size)
{
    const float* x     = (const float*)d_in[0];
    const float* w     = (const float*)d_in[1];
    const int*   shift = (const int*)  d_in[2];
    float*       out   = (float*)d_out;

    split_w_bf<<<36, 256>>>(w);    // 36*256 = 9216

    const int smem_bytes = MBAR_OFF + 16;   // 50704
    cudaFuncSetAttribute(conv1x7_bf,
                         cudaFuncAttributeMaxDynamicSharedMemorySize, smem_bytes);

    dim3 grid(Hdim, 2, 2);   // 56 x 2 x 2 = 224 blocks
    conv1x7_bf<<<grid, 384, smem_bytes>>>(x, shift, out);
}

// round 13
// speedup vs baseline: 1.1924x; 1.0029x over previous
#include <cuda_runtime.h>
#include <cuda_bf16.h>

// Grouped 1x7 conv (NCHW, groups=2, shared weights) + roll(H), tensor cores
// (m16n8k16 BF16, 3xBF16 split: hh + hl + lh, fp32 accumulate).
//
// K reordered as k = ic*8 + kw' (kw' 0..7, kw'=7 zero) -> bf16x2 pairs are
// adjacent kw -> B pairs = adjacent pixels, K' = 192 = 12 k16-chunks.
//
// R13: (a) PDL — splitter signals launch_dependents; main kernel overlaps its
//      x staging with the splitter, griddepcontrol.wait before the weight TMA.
//      (b) 2-deep double buffer on per-chunk LDS operands.

#define Hdim 56
#define Wdim 56
#define HW   3136
#define ICg  24

#define SWP  100   // u64 stride per oc row (96 used)
#define SXP  64    // u64 stride per ic row of x pairs

#define W_TILE_BYTES (48 * SWP * 8)              // 38400
#define SX_BYTES     (ICg * SXP * 8)             // 12288
#define MBAR_OFF     (W_TILE_BYTES + SX_BYTES)   // 50688

__device__ __align__(16) uint2 g_wsplit[96 * SWP];   // 76.8 KB scratch

__device__ __forceinline__ unsigned bf16bits(float v) {
    return (unsigned)__bfloat16_as_ushort(__float2bfloat16_rn(v));
}

__device__ __forceinline__ uint2 split_pack(float v0, float v1) {
    unsigned h0 = bf16bits(v0);
    unsigned h1 = bf16bits(v1);
    float r0 = v0 - __bfloat162float(__ushort_as_bfloat16((unsigned short)h0));
    float r1 = v1 - __bfloat162float(__ushort_as_bfloat16((unsigned short)h1));
    unsigned l0 = bf16bits(r0);
    unsigned l1 = bf16bits(r1);
    return make_uint2(h0 | (h1 << 16), l0 | (l1 << 16));
}

__device__ __forceinline__ void mma_bf16(float c[4],
                                         unsigned a0, unsigned a1,
                                         unsigned a2, unsigned a3,
                                         unsigned b0, unsigned b1) {
    asm volatile(
        "mma.sync.aligned.m16n8k16.row.col.f32.bf16.bf16.f32 "
        "{%0,%1,%2,%3},{%4,%5,%6,%7},{%8,%9},{%0,%1,%2,%3};"
        : "+f"(c[0]), "+f"(c[1]), "+f"(c[2]), "+f"(c[3])
        : "r"(a0), "r"(a1), "r"(a2), "r"(a3), "r"(b0), "r"(b1));
}

__global__ __launch_bounds__(256, 4)
void split_w_bf(const float* __restrict__ w)
{
    int i = blockIdx.x * 256 + threadIdx.x;     // 36*256 = 9216 exactly
    int oc = i / 96;
    int j  = i - oc * 96;          // j = ic*4 + t, pair kw' = 2t, 2t+1
    int ic = j >> 2;
    int t  = j & 3;
    const float* wp = w + ic * 672 + oc * 7;
    float v0 = wp[2 * t];
    float v1 = (2 * t + 1 < 7) ? wp[2 * t + 1] : 0.f;
    g_wsplit[oc * SWP + j] = split_pack(v0, v1);

    __threadfence();
    asm volatile("griddepcontrol.launch_dependents;");
}

__global__ __launch_bounds__(384, 2)
void conv1x7_bf(const float* __restrict__ x,
                const int* __restrict__ shift, float* __restrict__ out)
{
    extern __shared__ char smem[];
    uint2* swq = (uint2*)smem;                       // [48][SWP]
    uint2* sxp = (uint2*)(smem + W_TILE_BYTES);      // [24][SXP]

    unsigned smem_base;
    asm("{ .reg .u64 t; cvta.to.shared.u64 t, %1; cvt.u32.u64 %0, t; }"
        : "=r"(smem_base) : "l"(smem));
    const unsigned mbar = smem_base + MBAR_OFF;

    const int tid = threadIdx.x;
    const int h   = blockIdx.x;
    const int g   = blockIdx.y;
    const int mh  = blockIdx.z;      // oc in [mh*48, mh*48+48)

    if (tid == 0) {
        asm volatile("mbarrier.init.shared.b64 [%0], 1;" :: "r"(mbar) : "memory");
    }

    // ---- stage x row (independent of splitter -> overlaps it under PDL) ----
    const float* xrow = x + (size_t)g * (ICg * HW) + h * Wdim;
    #pragma unroll
    for (int it = 0; it < 4; it++) {                 // 4*384 = 1536
        int i  = it * 384 + tid;
        int ic = i >> 6;
        int p  = i & 63;
        int w0 = p - 3, w1 = p - 2;
        float v0 = (w0 >= 0 && w0 < Wdim) ? xrow[ic * HW + w0] : 0.f;
        float v1 = (w1 >= 0 && w1 < Wdim) ? xrow[ic * HW + w1] : 0.f;
        sxp[ic * SXP + p] = split_pack(v0, v1);
    }

    // ---- wait for splitter (PDL), then fetch weights with one TMA bulk ----
    asm volatile("griddepcontrol.wait;" ::: "memory");
    __syncthreads();   // x stores + mbar init visible to all
    if (tid == 0) {
        asm volatile("fence.proxy.async.shared::cta;" ::: "memory");
        asm volatile("mbarrier.arrive.expect_tx.shared.b64 _, [%0], %1;"
                     :: "r"(mbar), "r"((unsigned)W_TILE_BYTES) : "memory");
        asm volatile(
            "cp.async.bulk.shared::cta.global.mbarrier::complete_tx::bytes "
            "[%0], [%1], %2, [%3];"
            :: "r"(smem_base), "l"(g_wsplit + mh * 48 * SWP),
               "r"((unsigned)W_TILE_BYTES), "r"(mbar) : "memory");
    }

    // wait for the bulk copy (phase 0)
    {
        unsigned done;
        asm volatile(
            "{\n\t.reg .pred p;\n\t"
            "mbarrier.try_wait.parity.acquire.cta.shared::cta.b64 p, [%1], 0;\n\t"
            "selp.b32 %0, 1, 0, p;\n\t}"
            : "=r"(done) : "r"(mbar) : "memory");
        while (!done) {
            asm volatile(
                "{\n\t.reg .pred p;\n\t"
                "mbarrier.try_wait.parity.acquire.cta.shared::cta.b64 p, [%1], 0, 0x989680;\n\t"
                "selp.b32 %0, 1, 0, p;\n\t}"
                : "=r"(done) : "r"(mbar) : "memory");
        }
    }

    const int wid  = tid >> 5;        // 0..11
    const int mt   = wid >> 2;        // m-tile 0..2
    const int nq   = wid & 3;         // 0..3
    const int nf   = (nq == 3) ? 1 : 2;
    const int nt0  = nq * 2;          // frags nt0..nt0+nf-1 (7 total)
    const int lane = tid & 31;
    const int lg   = lane >> 2;       // 0..7
    const int lk   = lane & 3;        // 0..3

    const uint2* A0p = swq + (mt * 16 + lg) * SWP + lk;   // row lg
    const uint2* A1p = A0p + 8 * SWP;                     // row lg+8
    const int pb0 = nt0 * 8 + lg + 2 * lk;                // B pixel index

    float c[2][4];
    #pragma unroll
    for (int f = 0; f < 2; f++)
        #pragma unroll
        for (int q = 0; q < 4; q++) c[f][q] = 0.f;

    // ---- double-buffered mainloop over 12 k16-chunks ----
    uint2 A[2][4], B0[2][2], B1[2][2];

    {   // prologue: load chunk 0 into buffer 0
        A[0][0] = A0p[0];
        A[0][1] = A1p[0];
        A[0][2] = A0p[4];
        A[0][3] = A1p[4];
        const uint2* b0p = sxp;
        const uint2* b1p = sxp + SXP;
        #pragma unroll
        for (int f = 0; f < 2; f++) {
            if (f < nf) {
                B0[0][f] = b0p[pb0 + f * 8];
                B1[0][f] = b1p[pb0 + f * 8];
            }
        }
    }

    #pragma unroll
    for (int ks = 0; ks < 12; ks++) {
        const int cur = ks & 1;
        const int nxt = cur ^ 1;

        if (ks < 11) {   // prefetch next chunk
            const int j = (ks + 1) * 8;
            A[nxt][0] = A0p[j];
            A[nxt][1] = A1p[j];
            A[nxt][2] = A0p[j + 4];
            A[nxt][3] = A1p[j + 4];
            const uint2* b0p = sxp + (2 * (ks + 1)) * SXP;
            const uint2* b1p = b0p + SXP;
            #pragma unroll
            for (int f = 0; f < 2; f++) {
                if (f < nf) {
                    B0[nxt][f] = b0p[pb0 + f * 8];
                    B1[nxt][f] = b1p[pb0 + f * 8];
                }
            }
        }

        // hh
        #pragma unroll
        for (int f = 0; f < 2; f++)
            if (f < nf)
                mma_bf16(c[f], A[cur][0].x, A[cur][1].x, A[cur][2].x, A[cur][3].x,
                         B0[cur][f].x, B1[cur][f].x);
        // hl
        #pragma unroll
        for (int f = 0; f < 2; f++)
            if (f < nf)
                mma_bf16(c[f], A[cur][0].x, A[cur][1].x, A[cur][2].x, A[cur][3].x,
                         B0[cur][f].y, B1[cur][f].y);
        // lh
        #pragma unroll
        for (int f = 0; f < 2; f++)
            if (f < nf)
                mma_bf16(c[f], A[cur][0].y, A[cur][1].y, A[cur][2].y, A[cur][3].y,
                         B0[cur][f].x, B1[cur][f].x);
    }

    // ---- roll + store ----
    const int s = *shift;
    int ho = (h + s) % Hdim;
    if (ho < 0) ho += Hdim;

    float* ob = out + (size_t)(g * 96 + mh * 48 + mt * 16 + lg) * HW
                    + ho * Wdim + (nt0 * 8 + 2 * lk);
    #pragma unroll
    for (int f = 0; f < 2; f++) {
        if (f < nf) {
            *(float2*)(ob + f * 8)          = make_float2(c[f][0], c[f][1]);
            *(float2*)(ob + 8 * HW + f * 8) = make_float2(c[f][2], c[f][3]);
        }
    }
}

extern "C" void kernel_launch(void* const* d_in, const int* in_sizes, int n_in,
                              void* d_out, int out_size)
{
    const float* x     = (const float*)d_in[0];
    const float* w     = (const float*)d_in[1];
    const int*   shift = (const int*)  d_in[2];
    float*       out   = (float*)d_out;

    split_w_bf<<<36, 256>>>(w);    // 36*256 = 9216

    const int smem_bytes = MBAR_OFF + 16;   // 50704
    static int smem_set = 0;
    if (!smem_set) {
        cudaFuncSetAttribute(conv1x7_bf,
                             cudaFuncAttributeMaxDynamicSharedMemorySize, smem_bytes);
        smem_set = 1;
    }

    // PDL launch: overlap main kernel's x staging with the splitter
    cudaLaunchConfig_t cfg = {};
    cfg.gridDim  = dim3(Hdim, 2, 2);   // 224 blocks
    cfg.blockDim = dim3(384, 1, 1);
    cfg.dynamicSmemBytes = smem_bytes;
    cfg.stream = 0;
    cudaLaunchAttribute attr[1];
    attr[0].id = cudaLaunchAttributeProgrammaticStreamSerialization;
    attr[0].val.programmaticStreamSerializationAllowed = 1;
    cfg.attrs = attr;
    cfg.numAttrs = 1;
    cudaLaunchKernelEx(&cfg, conv1x7_bf, x, shift, out);
}